// round 1
// baseline (speedup 1.0000x reference)
#include <cuda_runtime.h>
#include <cuda_bf16.h>
#include <cstdint>

// Problem constants (match reference)
#define Bn 128
#define Qn 200
#define Cn 92
#define NTHREADS 256
#define FINF 1e9f

struct Smem {
    float cost[Qn * Qn];   // 160000 B  cost[i*Qn + j], i=row(pred), j=col(target)
    float u[Qn + 1];       // row potentials (1-based, u[0] sentinel)
    int   p[Qn + 1];       // p[j] = row matched to column j (1-based), 0 = free
    int   way[Qn + 1];     // augmenting-path back-pointers (written at row end)
    int   tc[Qn];          // target classes
    float lse[Qn];         // per-row logsumexp of pred_cat
    float pb[Qn * 4];      // pred bboxes
    float tb[Qn * 4];      // target bboxes
    float wbest[8];        // per-warp argmin value
    int   wbj[8];          // per-warp argmin index
    float s_delta;
    int   s_j1;
};

__global__ __launch_bounds__(NTHREADS, 1)
void hungarian_loss_kernel(const float* __restrict__ pred_cat,
                           const float* __restrict__ pred_bbox,
                           const int*   __restrict__ tar_cat,
                           const float* __restrict__ tar_bbox,
                           float* __restrict__ out) {
    extern __shared__ char smem_raw[];
    Smem* sm = reinterpret_cast<Smem*>(smem_raw);

    const int b    = blockIdx.x;
    const int tid  = threadIdx.x;
    const int lane = tid & 31;
    const int wid  = tid >> 5;

    // ---------------- Phase A: stage small tensors, per-row logsumexp -------
    for (int i = tid; i < Qn; i += NTHREADS) sm->tc[i] = tar_cat[b * Qn + i];
    for (int i = tid; i < Qn * 4; i += NTHREADS) {
        sm->pb[i] = pred_bbox[(size_t)b * Qn * 4 + i];
        sm->tb[i] = tar_bbox[(size_t)b * Qn * 4 + i];
    }

    // warp-per-row logsumexp over C=92 classes (coalesced within warp)
    for (int row = wid; row < Qn; row += (NTHREADS / 32)) {
        const float* x = pred_cat + ((size_t)b * Qn + row) * Cn;
        float m = -FINF;
        for (int c = lane; c < Cn; c += 32) m = fmaxf(m, x[c]);
        #pragma unroll
        for (int o = 16; o; o >>= 1) m = fmaxf(m, __shfl_xor_sync(0xFFFFFFFFu, m, o));
        float s = 0.f;
        for (int c = lane; c < Cn; c += 32) s += expf(x[c] - m);
        #pragma unroll
        for (int o = 16; o; o >>= 1) s += __shfl_xor_sync(0xFFFFFFFFu, s, o);
        if (lane == 0) sm->lse[row] = m + logf(s);
    }
    __syncthreads();

    // ---------------- Phase B: cost matrix into smem ------------------------
    for (int idx = tid; idx < Qn * Qn; idx += NTHREADS) {
        const int i = idx / Qn;
        const int j = idx - i * Qn;
        const int cls = sm->tc[j];
        const float ce = sm->lse[i] - pred_cat[((size_t)b * Qn + i) * Cn + cls];
        float sl1 = 0.f;
        #pragma unroll
        for (int k = 0; k < 4; k++) {
            const float d  = sm->pb[i * 4 + k] - sm->tb[j * 4 + k];
            const float ad = fabsf(d);
            sl1 += (ad < 1.f) ? 0.5f * d * d : (ad - 0.5f);
        }
        const float mask = (cls != 0) ? 1.f : 0.f;
        sm->cost[idx] = ce + sl1 * mask;
    }

    // init potentials / matching
    for (int j = tid; j <= Qn; j += NTHREADS) { sm->u[j] = 0.f; sm->p[j] = 0; }

    // Column-owned state lives in registers of thread `tid` (column j == tid).
    float v_reg = 0.f;           // v[tid]
    __syncthreads();

    // ---------------- Phase C: JV Hungarian, one row at a time --------------
    for (int i = 1; i <= Qn; i++) {
        if (tid == 0) sm->p[0] = i;
        float minv_reg = FINF;
        int   way_reg  = 0;
        bool  used     = false;
        int   j0       = 0;
        __syncthreads();   // p[0] visible; u writes from previous row visible

        int j_last;
        while (true) {
            if (tid == j0) used = true;           // column j0 enters the tree
            const int   i0  = sm->p[j0];
            const float ui0 = sm->u[i0];

            float best = FINF;
            int   bj   = tid;
            if (tid >= 1 && tid <= Qn && !used) {
                const float cur = sm->cost[(i0 - 1) * Qn + (tid - 1)] - ui0 - v_reg;
                if (cur < minv_reg) { minv_reg = cur; way_reg = j0; }
                best = minv_reg;
            }
            // warp-level (value,index) min, tie -> smaller index (match jnp.argmin)
            #pragma unroll
            for (int o = 16; o; o >>= 1) {
                const float ov = __shfl_xor_sync(0xFFFFFFFFu, best, o);
                const int   oj = __shfl_xor_sync(0xFFFFFFFFu, bj, o);
                if (ov < best || (ov == best && oj < bj)) { best = ov; bj = oj; }
            }
            if (lane == 0) { sm->wbest[wid] = best; sm->wbj[wid] = bj; }
            __syncthreads();                       // (A)
            if (wid == 0) {
                float bv  = (lane < (NTHREADS / 32)) ? sm->wbest[lane] : FINF;
                int   bj2 = (lane < (NTHREADS / 32)) ? sm->wbj[lane]   : 0x7fffffff;
                #pragma unroll
                for (int o = 16; o; o >>= 1) {
                    const float ov = __shfl_xor_sync(0xFFFFFFFFu, bv, o);
                    const int   oj = __shfl_xor_sync(0xFFFFFFFFu, bj2, o);
                    if (ov < bv || (ov == bv && oj < bj2)) { bv = ov; bj2 = oj; }
                }
                if (lane == 0) { sm->s_delta = bv; sm->s_j1 = bj2; }
            }
            __syncthreads();                       // (B)
            const float delta = sm->s_delta;
            const int   j1    = sm->s_j1;

            if (tid <= Qn) {
                if (used) {
                    sm->u[sm->p[tid]] += delta;    // distinct rows: race-free
                    v_reg -= delta;
                } else {
                    minv_reg -= delta;
                }
            }
            j0 = j1;
            const bool done = (sm->p[j0] == 0);    // p untouched during Dijkstra
            __syncthreads();                       // (C) u writes visible next iter
            if (done) { j_last = j0; break; }
        }

        // dump register-resident back-pointers, then serial augmentation
        if (tid >= 1 && tid <= Qn) sm->way[tid] = way_reg;
        __syncthreads();
        if (tid == 0) {
            int j = j_last;
            while (j) {
                const int jp = sm->way[j];
                sm->p[j] = sm->p[jp];
                j = jp;
            }
        }
        __syncthreads();
    }

    // ---------------- Phase D: gather matched costs -------------------------
    // p[j] (1-based) = row matched to column j; p[1..Qn] rows form a permutation.
    for (int j = tid + 1; j <= Qn; j += NTHREADS) {
        const int row = sm->p[j] - 1;
        out[b * Qn + row] = sm->cost[row * Qn + (j - 1)];
    }
}

extern "C" void kernel_launch(void* const* d_in, const int* in_sizes, int n_in,
                              void* d_out, int out_size) {
    const float* pred_cat  = (const float*)d_in[0];
    const float* pred_bbox = (const float*)d_in[1];
    const int*   tar_cat   = (const int*)d_in[2];
    const float* tar_bbox  = (const float*)d_in[3];
    float* out = (float*)d_out;

    static bool attr_set = false;
    if (!attr_set) {
        cudaFuncSetAttribute(hungarian_loss_kernel,
                             cudaFuncAttributeMaxDynamicSharedMemorySize,
                             (int)sizeof(Smem));
        attr_set = true;
    }
    hungarian_loss_kernel<<<Bn, NTHREADS, sizeof(Smem)>>>(
        pred_cat, pred_bbox, tar_cat, tar_bbox, out);
}